// round 14
// baseline (speedup 1.0000x reference)
#include <cuda_runtime.h>
#include <cuda_fp16.h>
#include <math.h>

#define NN    8192
#define INC   512
#define SLOT  192
#define PMASK 0x7FFFFFFF

// ---------------- scratch (device globals) -----------------------------------
__device__ __half2 g_h1h[NN * 32];
__device__ float g_als1[NN * 8];
__device__ float g_ald1[NN * 8];
__device__ __half2 g_h2h[NN * 32];
__device__ float g_als2[NN];
__device__ float g_ald2[NN];
__device__ float g_x2[NN * 64];
__device__ float g_s2[NN * 64];
__device__ __half2 g_s2h[NN * 32];
__device__ float g_tmp2[NN * 64];
__device__ float g_pool[2 * 4096];
__device__ float g_partA[128 * 4096];
__device__ float g_partX[128 * 4096];
__device__ int   g_cnt[NN];                 // zero-initialized; re-zeroed each launch in MEGA P5
__device__ __align__(16) int g_slot[NN * SLOT];
__device__ unsigned g_barArr;               // cumulative across replays (generation math)
__device__ unsigned g_barRel;

// ---------------- helpers ----------------------------------------------------
__device__ __forceinline__ float lrelu(float v) { return v > 0.f ? v : 0.2f * v; }

__device__ __forceinline__ void fma2(unsigned long long& d, unsigned long long a, unsigned long long b) {
    asm("fma.rn.f32x2 %0, %1, %2, %0;" : "+l"(d) : "l"(a), "l"(b));
}
__device__ __forceinline__ unsigned long long splat2(float a) {
    unsigned long long r;
    asm("mov.b64 %0, {%1, %1};" : "=l"(r) : "f"(a));
    return r;
}
__device__ __forceinline__ float4 ldh4(const __half2* p) {
    uint2 u = *(const uint2*)p;
    float2 a = __half22float2(*reinterpret_cast<__half2*>(&u.x));
    float2 b = __half22float2(*reinterpret_cast<__half2*>(&u.y));
    return make_float4(a.x, a.y, b.x, b.y);
}

// grid barrier: single atomic arrive, acquire-load polling
__device__ __forceinline__ void gridBar(int G) {
    __syncthreads();
    if (threadIdx.x == 0) {
        __threadfence();
        unsigned arr = atomicAdd(&g_barArr, 1u) + 1u;
        unsigned gen = (arr + (unsigned)G - 1u) / (unsigned)G;
        if (arr == gen * (unsigned)G) {
            atomicAdd(&g_barRel, 1u);
        } else {
            unsigned r;
            do {
                __nanosleep(128);
                asm volatile("ld.acquire.gpu.u32 %0, [%1];" : "=r"(r) : "l"(&g_barRel));
            } while (r < gen);
        }
    }
    __syncthreads();
}

// ---------------- bucket build (8 edges/thread) --------------------------------
__global__ void perm_kernel(const int* __restrict__ ei, int E) {
    int i = blockIdx.x * blockDim.x + threadIdx.x;
    int q8 = E >> 3;
    if (i < q8) {
        int4 sa = __ldg((const int4*)ei + 2 * i);
        int4 sb = __ldg((const int4*)ei + 2 * i + 1);
        int4 da = __ldg((const int4*)(ei + E) + 2 * i);
        int4 db = __ldg((const int4*)(ei + E) + 2 * i + 1);
        int p0 = atomicAdd(&g_cnt[da.x], 1);
        int p1 = atomicAdd(&g_cnt[da.y], 1);
        int p2 = atomicAdd(&g_cnt[da.z], 1);
        int p3 = atomicAdd(&g_cnt[da.w], 1);
        int p4 = atomicAdd(&g_cnt[db.x], 1);
        int p5 = atomicAdd(&g_cnt[db.y], 1);
        int p6 = atomicAdd(&g_cnt[db.z], 1);
        int p7 = atomicAdd(&g_cnt[db.w], 1);
        if (p0 < SLOT) g_slot[da.x * SLOT + p0] = sa.x;
        if (p1 < SLOT) g_slot[da.y * SLOT + p1] = sa.y;
        if (p2 < SLOT) g_slot[da.z * SLOT + p2] = sa.z;
        if (p3 < SLOT) g_slot[da.w * SLOT + p3] = sa.w;
        if (p4 < SLOT) g_slot[db.x * SLOT + p4] = sb.x;
        if (p5 < SLOT) g_slot[db.y * SLOT + p5] = sb.y;
        if (p6 < SLOT) g_slot[db.z * SLOT + p6] = sb.z;
        if (p7 < SLOT) g_slot[db.w * SLOT + p7] = sb.w;
    } else if (i < q8 + NN) {
        int n = i - q8;
        int p = atomicAdd(&g_cnt[n], 1);
        if (p < SLOT) g_slot[n * SLOT + p] = n | 0x80000000;
    }
}

// ---------------- sgemm1 (Kd=512, 32-row tiles) + att1, fp16 h1 out -------------
__global__ void sgemm1_att(const float* __restrict__ A, const float* __restrict__ B,
                           const float* __restrict__ asrc, const float* __restrict__ adst) {
    __shared__ float As[32][36];
    __shared__ float Bs[32][64];
    __shared__ float Cs[32][66];
    int tid = threadIdx.x;
    int row0 = blockIdx.x * 32;
    int ty = tid >> 4, tx = tid & 15;
    unsigned long long acc[2][2] = {};
    for (int k0 = 0; k0 < INC; k0 += 32) {
        #pragma unroll
        for (int i = tid; i < 32 * 32; i += 256) {
            int m = i >> 5, k = i & 31;
            As[k][m] = A[(row0 + m) * INC + k0 + k];
        }
        #pragma unroll
        for (int i = tid; i < 32 * 64; i += 256) {
            int k = i >> 6, n = i & 63;
            Bs[k][n] = B[(k0 + k) * 64 + n];
        }
        __syncthreads();
        #pragma unroll
        for (int k = 0; k < 32; k++) {
            float a0 = As[k][ty * 2], a1 = As[k][ty * 2 + 1];
            const unsigned long long* bp = (const unsigned long long*)&Bs[k][tx * 4];
            unsigned long long b01 = bp[0], b23 = bp[1];
            unsigned long long s0 = splat2(a0), s1 = splat2(a1);
            fma2(acc[0][0], s0, b01); fma2(acc[0][1], s0, b23);
            fma2(acc[1][0], s1, b01); fma2(acc[1][1], s1, b23);
        }
        __syncthreads();
    }
    #pragma unroll
    for (int i = 0; i < 2; i++) {
        float2 lo = *(float2*)&acc[i][0];
        float2 hi = *(float2*)&acc[i][1];
        __half2 ha = __floats2half2_rn(lo.x, lo.y);
        __half2 hb = __floats2half2_rn(hi.x, hi.y);
        uint2 u;
        u.x = *reinterpret_cast<unsigned*>(&ha);
        u.y = *reinterpret_cast<unsigned*>(&hb);
        *(uint2*)(g_h1h + (row0 + ty * 2 + i) * 32 + tx * 2) = u;
        unsigned long long* sp = (unsigned long long*)&Cs[ty * 2 + i][tx * 4];
        sp[0] = acc[i][0]; sp[1] = acc[i][1];
    }
    __syncthreads();
    {
        int n = tid >> 3, h = tid & 7;
        const float* hp = &Cs[n][h * 8];
        float s = 0.f, d = 0.f;
        #pragma unroll
        for (int c = 0; c < 8; c++) {
            s += hp[c] * __ldg(asrc + h * 8 + c);
            d += hp[c] * __ldg(adst + h * 8 + c);
        }
        g_als1[(row0 + n) * 8 + h] = s;
        g_ald1[(row0 + n) * 8 + h] = d;
    }
}

// ---------------- MEGA: gather1+sgemm2 | gather2 | adj | pool | reduce | final --
__global__ void __launch_bounds__(256, 4)
mega_kernel(const float* __restrict__ b1, const float* __restrict__ W2,
            const float* __restrict__ asrc2, const float* __restrict__ adst2,
            const float* __restrict__ b2, float* __restrict__ out, int G) {
    __shared__ __align__(16) float W2s[64 * 64];
    __shared__ float A2s[128];
    __shared__ __align__(16) float srow[8][64];
    __shared__ uint2 stg[8][32];
    int tid = threadIdx.x;
    int wid = tid >> 5;
    int lane = tid & 31;
    int epar = lane >> 4;
    int sub = lane & 15;
    int c0 = sub * 4;
    int gw0 = blockIdx.x * 8 + wid;
    int nwarp = G * 8;
    float* outS = out + 2 * 4096;

    #pragma unroll
    for (int i = tid; i < 64 * 64 / 4; i += 256)
        ((float4*)W2s)[i] = __ldg((const float4*)W2 + i);
    if (tid < 64)       A2s[tid] = __ldg(asrc2 + tid);
    else if (tid < 128) A2s[tid] = __ldg(adst2 + tid - 64);
    __syncthreads();

    // ---- P1: gather1 + sgemm2-row + att2 ----
    for (int node = gw0; node < NN; node += nwarp) {
        int h = sub >> 1;
        int cnt = min(__ldg(g_cnt + node), SLOT);
        int base = node * SLOT;
        float ald = __ldg(g_ald1 + node * 8 + h);
        float4 acc = make_float4(0.f, 0.f, 0.f, 0.f);
        float den = 0.f;
        int e = 0;
        int4 P = (8 <= cnt) ? *(const int4*)(g_slot + base + 4 * epar) : make_int4(0, 0, 0, 0);
        for (; e + 8 <= cnt; e += 8) {
            int4 Pn = (e + 16 <= cnt) ? *(const int4*)(g_slot + base + e + 8 + 4 * epar) : P;
            int p0 = P.x & PMASK, p1 = P.y & PMASK, p2 = P.z & PMASK, p3 = P.w & PMASK;
            float s0 = __ldg(g_als1 + p0 * 8 + h);
            float s1 = __ldg(g_als1 + p1 * 8 + h);
            float s2 = __ldg(g_als1 + p2 * 8 + h);
            float s3 = __ldg(g_als1 + p3 * 8 + h);
            float4 h0 = ldh4(g_h1h + p0 * 32 + sub * 2);
            float4 h1 = ldh4(g_h1h + p1 * 32 + sub * 2);
            float4 h2 = ldh4(g_h1h + p2 * 32 + sub * 2);
            float4 h3 = ldh4(g_h1h + p3 * 32 + sub * 2);
            float w0 = __expf(lrelu(s0 + ald));
            float w1 = __expf(lrelu(s1 + ald));
            float w2 = __expf(lrelu(s2 + ald));
            float w3 = __expf(lrelu(s3 + ald));
            den += (w0 + w1) + (w2 + w3);
            acc.x += w0 * h0.x + w1 * h1.x + w2 * h2.x + w3 * h3.x;
            acc.y += w0 * h0.y + w1 * h1.y + w2 * h2.y + w3 * h3.y;
            acc.z += w0 * h0.z + w1 * h1.z + w2 * h2.z + w3 * h3.z;
            acc.w += w0 * h0.w + w1 * h1.w + w2 * h2.w + w3 * h3.w;
            P = Pn;
        }
        for (; e < cnt; e++) {
            if (epar == 0) {
                int p = g_slot[base + e] & PMASK;
                float w = __expf(lrelu(__ldg(g_als1 + p * 8 + h) + ald));
                float4 hv = ldh4(g_h1h + p * 32 + sub * 2);
                den += w;
                acc.x += w * hv.x; acc.y += w * hv.y;
                acc.z += w * hv.z; acc.w += w * hv.w;
            }
        }
        acc.x += __shfl_xor_sync(0xffffffffu, acc.x, 16);
        acc.y += __shfl_xor_sync(0xffffffffu, acc.y, 16);
        acc.z += __shfl_xor_sync(0xffffffffu, acc.z, 16);
        acc.w += __shfl_xor_sync(0xffffffffu, acc.w, 16);
        den   += __shfl_xor_sync(0xffffffffu, den, 16);
        den += 1e-16f;
        float4 bb = *(const float4*)(b1 + c0);
        float4 v;
        v.x = acc.x / den + bb.x;
        v.y = acc.y / den + bb.y;
        v.z = acc.z / den + bb.z;
        v.w = acc.w / den + bb.w;
        v.x = v.x > 0.f ? v.x : (__expf(v.x) - 1.f);
        v.y = v.y > 0.f ? v.y : (__expf(v.y) - 1.f);
        v.z = v.z > 0.f ? v.z : (__expf(v.z) - 1.f);
        v.w = v.w > 0.f ? v.w : (__expf(v.w) - 1.f);
        if (epar == 0) *(float4*)&srow[wid][c0] = v;
        __syncwarp();
        float4 ha = make_float4(0.f, 0.f, 0.f, 0.f);
        #pragma unroll
        for (int k4 = 0; k4 < 16; k4++) {
            float4 r = *(const float4*)&srow[wid][k4 * 4];
            float4 w0 = *(const float4*)&W2s[(k4 * 4 + 0) * 64 + c0];
            float4 w1 = *(const float4*)&W2s[(k4 * 4 + 1) * 64 + c0];
            float4 w2 = *(const float4*)&W2s[(k4 * 4 + 2) * 64 + c0];
            float4 w3 = *(const float4*)&W2s[(k4 * 4 + 3) * 64 + c0];
            ha.x += r.x * w0.x + r.y * w1.x + r.z * w2.x + r.w * w3.x;
            ha.y += r.x * w0.y + r.y * w1.y + r.z * w2.y + r.w * w3.y;
            ha.z += r.x * w0.z + r.y * w1.z + r.z * w2.z + r.w * w3.z;
            ha.w += r.x * w0.w + r.y * w1.w + r.z * w2.w + r.w * w3.w;
        }
        __syncwarp();
        if (epar == 0) {
            __half2 hza = __floats2half2_rn(ha.x, ha.y);
            __half2 hzb = __floats2half2_rn(ha.z, ha.w);
            uint2 u;
            u.x = *reinterpret_cast<unsigned*>(&hza);
            u.y = *reinterpret_cast<unsigned*>(&hzb);
            *(uint2*)(g_h2h + node * 32 + sub * 2) = u;
        }
        float s = ha.x * A2s[c0] + ha.y * A2s[c0 + 1] + ha.z * A2s[c0 + 2] + ha.w * A2s[c0 + 3];
        float d = ha.x * A2s[64 + c0] + ha.y * A2s[64 + c0 + 1]
                + ha.z * A2s[64 + c0 + 2] + ha.w * A2s[64 + c0 + 3];
        #pragma unroll
        for (int o = 1; o < 16; o <<= 1) {
            s += __shfl_xor_sync(0xffffffffu, s, o);
            d += __shfl_xor_sync(0xffffffffu, d, o);
        }
        if (lane == 0) { g_als2[node] = s; g_ald2[node] = d; }
    }
    gridBar(G);

    // ---- P2: gather2 (pipelined two-phase staged) ----
    for (int node = gw0; node < NN; node += nwarp) {
        int cnt = min(__ldg(g_cnt + node), SLOT);
        int base = node * SLOT;
        float ald = __ldg(g_ald2 + node);
        float4 acc = make_float4(0.f, 0.f, 0.f, 0.f);
        float den = 0.f;
        int p_cur = 0;
        float w_cur = 0.f;
        if (cnt > 0) {
            if (lane < cnt) p_cur = g_slot[base + lane] & PMASK;
            float als = __ldg(g_als2 + p_cur);
            w_cur = (lane < cnt) ? __expf(lrelu(als + ald)) : 0.f;
        }
        for (int e0 = 0; e0 < cnt; e0 += 32) {
            den += w_cur;
            stg[wid][lane] = make_uint2(__float_as_uint(w_cur), (unsigned)p_cur << 5);
            __syncwarp();
            int en = e0 + 32 + lane;
            bool vn = (en < cnt);
            int p_n = vn ? (g_slot[base + en] & PMASK) : 0;
            float als_n = __ldg(g_als2 + p_n);
            int lim = min(32, cnt - e0);
            int j = 0;
            for (; j + 8 <= lim; j += 8) {
                uint2 u0 = stg[wid][j + 0 + epar];
                uint2 u1 = stg[wid][j + 2 + epar];
                uint2 u2 = stg[wid][j + 4 + epar];
                uint2 u3 = stg[wid][j + 6 + epar];
                float4 h0 = ldh4(g_h2h + u0.y + sub * 2);
                float4 h1 = ldh4(g_h2h + u1.y + sub * 2);
                float4 h2v = ldh4(g_h2h + u2.y + sub * 2);
                float4 h3 = ldh4(g_h2h + u3.y + sub * 2);
                float w0 = __uint_as_float(u0.x);
                float w1 = __uint_as_float(u1.x);
                float w2 = __uint_as_float(u2.x);
                float w3 = __uint_as_float(u3.x);
                acc.x += w0 * h0.x + w1 * h1.x + w2 * h2v.x + w3 * h3.x;
                acc.y += w0 * h0.y + w1 * h1.y + w2 * h2v.y + w3 * h3.y;
                acc.z += w0 * h0.z + w1 * h1.z + w2 * h2v.z + w3 * h3.z;
                acc.w += w0 * h0.w + w1 * h1.w + w2 * h2v.w + w3 * h3.w;
            }
            for (; j < lim; j += 2) {
                uint2 u = stg[wid][j + epar];
                float wj = __uint_as_float(u.x);
                float4 hv = ldh4(g_h2h + u.y + sub * 2);
                acc.x += wj * hv.x; acc.y += wj * hv.y;
                acc.z += wj * hv.z; acc.w += wj * hv.w;
            }
            __syncwarp();
            w_cur = vn ? __expf(lrelu(als_n + ald)) : 0.f;
            p_cur = p_n;
        }
        acc.x += __shfl_xor_sync(0xffffffffu, acc.x, 16);
        acc.y += __shfl_xor_sync(0xffffffffu, acc.y, 16);
        acc.z += __shfl_xor_sync(0xffffffffu, acc.z, 16);
        acc.w += __shfl_xor_sync(0xffffffffu, acc.w, 16);
        #pragma unroll
        for (int o = 16; o > 0; o >>= 1) den += __shfl_xor_sync(0xffffffffu, den, o);
        den += 1e-16f;
        float4 bb = *(const float4*)(b2 + c0);
        float4 v;
        v.x = acc.x / den + bb.x;
        v.y = acc.y / den + bb.y;
        v.z = acc.z / den + bb.z;
        v.w = acc.w / den + bb.w;
        if (epar == 0) *(float4*)(g_x2 + node * 64 + c0) = v;
        float mx = fmaxf(fmaxf(v.x, v.y), fmaxf(v.z, v.w));
        #pragma unroll
        for (int o = 1; o < 16; o <<= 1) mx = fmaxf(mx, __shfl_xor_sync(0xffffffffu, mx, o));
        float e0v = __expf(v.x - mx), e1v = __expf(v.y - mx);
        float e2v = __expf(v.z - mx), e3v = __expf(v.w - mx);
        float sm = (e0v + e1v) + (e2v + e3v);
        #pragma unroll
        for (int o = 1; o < 16; o <<= 1) sm += __shfl_xor_sync(0xffffffffu, sm, o);
        float4 s;
        s.x = e0v / sm; s.y = e1v / sm; s.z = e2v / sm; s.w = e3v / sm;
        if (epar == 0) *(float4*)(outS + node * 64 + c0) = s;
        float m2 = fmaxf(fmaxf(s.x, s.y), fmaxf(s.z, s.w));
        #pragma unroll
        for (int o = 1; o < 16; o <<= 1) m2 = fmaxf(m2, __shfl_xor_sync(0xffffffffu, m2, o));
        float f0 = __expf(s.x - m2), f1 = __expf(s.y - m2);
        float f2 = __expf(s.z - m2), f3 = __expf(s.w - m2);
        float sm2 = (f0 + f1) + (f2 + f3);
        #pragma unroll
        for (int o = 1; o < 16; o <<= 1) sm2 += __shfl_xor_sync(0xffffffffu, sm2, o);
        float4 z;
        z.x = f0 / sm2; z.y = f1 / sm2; z.z = f2 / sm2; z.w = f3 / sm2;
        if (epar == 0) {
            *(float4*)(g_s2 + node * 64 + c0) = z;
            __half2 hza = __floats2half2_rn(z.x, z.y);
            __half2 hzb = __floats2half2_rn(z.z, z.w);
            uint2 u;
            u.x = *reinterpret_cast<unsigned*>(&hza);
            u.y = *reinterpret_cast<unsigned*>(&hzb);
            *(uint2*)(g_s2h + node * 32 + sub * 2) = u;
        }
    }
    gridBar(G);

    // ---- P3: adjacency gather ----
    for (int node = gw0; node < NN; node += nwarp) {
        int cnt = min(__ldg(g_cnt + node), SLOT);
        int base = node * SLOT;
        float4 acc = make_float4(0.f, 0.f, 0.f, 0.f);
        int e = 0;
        int4 P = (8 <= cnt) ? *(const int4*)(g_slot + base + 4 * epar)
                            : make_int4(-1, -1, -1, -1);
        for (; e + 8 <= cnt; e += 8) {
            int4 Pn = (e + 16 <= cnt) ? *(const int4*)(g_slot + base + e + 8 + 4 * epar) : P;
            float4 f0 = ldh4(g_s2h + (P.x & PMASK) * 32 + sub * 2);
            float4 f1 = ldh4(g_s2h + (P.y & PMASK) * 32 + sub * 2);
            float4 f2 = ldh4(g_s2h + (P.z & PMASK) * 32 + sub * 2);
            float4 f3 = ldh4(g_s2h + (P.w & PMASK) * 32 + sub * 2);
            if (P.x >= 0) { acc.x += f0.x; acc.y += f0.y; acc.z += f0.z; acc.w += f0.w; }
            if (P.y >= 0) { acc.x += f1.x; acc.y += f1.y; acc.z += f1.z; acc.w += f1.w; }
            if (P.z >= 0) { acc.x += f2.x; acc.y += f2.y; acc.z += f2.z; acc.w += f2.w; }
            if (P.w >= 0) { acc.x += f3.x; acc.y += f3.y; acc.z += f3.z; acc.w += f3.w; }
            P = Pn;
        }
        for (; e < cnt; e++) {
            if (epar == 0) {
                int p = g_slot[base + e];
                if (p >= 0) {
                    float4 fv = ldh4(g_s2h + (p & PMASK) * 32 + sub * 2);
                    acc.x += fv.x; acc.y += fv.y; acc.z += fv.z; acc.w += fv.w;
                }
            }
        }
        acc.x += __shfl_xor_sync(0xffffffffu, acc.x, 16);
        acc.y += __shfl_xor_sync(0xffffffffu, acc.y, 16);
        acc.z += __shfl_xor_sync(0xffffffffu, acc.z, 16);
        acc.w += __shfl_xor_sync(0xffffffffu, acc.w, 16);
        if (epar == 0)
            *(float4*)(g_tmp2 + node * 64 + sub * 4) = acc;
    }
    gridBar(G);

    // ---- P4: pool partials (A and X together; s2 row read once) ----
    for (int chunk = blockIdx.x; chunk < 128; chunk += G) {
        int i = tid >> 2;
        int jb = (tid & 3) * 16;
        int base = chunk * 64;
        float accA[16] = {}, accX[16] = {};
        for (int n = 0; n < 64; n++) {
            int node = base + n;
            float si = __ldg(g_s2 + node * 64 + i);
            const float4* t4 = (const float4*)(g_tmp2 + node * 64 + jb);
            const float4* x4 = (const float4*)(g_x2 + node * 64 + jb);
            #pragma unroll
            for (int q = 0; q < 4; q++) {
                float4 tv = __ldg(t4 + q), xv = __ldg(x4 + q);
                accA[q * 4 + 0] += si * tv.x; accA[q * 4 + 1] += si * tv.y;
                accA[q * 4 + 2] += si * tv.z; accA[q * 4 + 3] += si * tv.w;
                accX[q * 4 + 0] += si * xv.x; accX[q * 4 + 1] += si * xv.y;
                accX[q * 4 + 2] += si * xv.z; accX[q * 4 + 3] += si * xv.w;
            }
        }
        float* pa = g_partA + chunk * 4096;
        float* px = g_partX + chunk * 4096;
        #pragma unroll
        for (int u = 0; u < 16; u++) {
            pa[i * 64 + jb + u] = accA[u];
            px[i * 64 + jb + u] = accX[u];
        }
    }
    gridBar(G);

    // ---- P5: reduce partials + re-zero g_cnt for next launch ----
    for (int idx = blockIdx.x * 256 + tid; idx < 8192; idx += G * 256) {
        float s = 0.f;
        if (idx < 4096) {
            #pragma unroll 8
            for (int b = 0; b < 128; b++) s += g_partA[b * 4096 + idx];
        } else {
            int j = idx - 4096;
            #pragma unroll 8
            for (int b = 0; b < 128; b++) s += g_partX[b * 4096 + j];
        }
        g_pool[idx] = s;
    }
    for (int i = blockIdx.x * 256 + tid; i < NN; i += G * 256) g_cnt[i] = 0;
    gridBar(G);

    // ---- P6: finalize (block 0; full-block __syncthreads — no divergent sync) ----
    if (blockIdx.x == 0) {
        int i = tid;
        float sdi = 0.f;
        if (i < 64) {
            float rs = 0.f;
            for (int j = 0; j < 64; j++) {
                float v = (j == i) ? 0.f : g_pool[i * 64 + j];
                rs += v;
            }
            sdi = sqrtf(rs) + 1e-15f;
            srow[0][i] = sdi;
        }
        __syncthreads();
        if (i < 64) {
            for (int j = 0; j < 64; j++) {
                float v = (j == i) ? 0.f : g_pool[i * 64 + j];
                out[4096 + i * 64 + j] = v / srow[0][j] / sdi;
                out[i * 64 + j] = g_pool[4096 + i * 64 + j];
            }
        }
    }
}

// ---------------- launch --------------------------------------------------------
extern "C" void kernel_launch(void* const* d_in, const int* in_sizes, int n_in,
                              void* d_out, int out_size) {
    const float* x     = (const float*)d_in[0];
    const int*   ei    = (const int*)d_in[1];
    const float* W1    = (const float*)d_in[2];
    const float* asrc1 = (const float*)d_in[3];
    const float* adst1 = (const float*)d_in[4];
    const float* b1    = (const float*)d_in[5];
    const float* W2    = (const float*)d_in[6];
    const float* asrc2 = (const float*)d_in[7];
    const float* adst2 = (const float*)d_in[8];
    const float* b2    = (const float*)d_in[9];
    float* out = (float*)d_out;

    const int E = in_sizes[1] / 2;       // 524288
    const int q8 = (E >> 3) + NN;

    static bool inited = false;
    static cudaStream_t sB;
    static cudaEvent_t evA, evB;
    static int G = 0;
    if (!inited) {
        cudaStreamCreateWithFlags(&sB, cudaStreamNonBlocking);
        cudaEventCreateWithFlags(&evA, cudaEventDisableTiming);
        cudaEventCreateWithFlags(&evB, cudaEventDisableTiming);
        int dev = 0, sms = 0, bpm = 0;
        cudaGetDevice(&dev);
        cudaDeviceGetAttribute(&sms, cudaDevAttrMultiProcessorCount, dev);
        cudaOccupancyMaxActiveBlocksPerMultiprocessor(&bpm, mega_kernel, 256, 0);
        if (bpm < 1) bpm = 1;
        G = sms * bpm;
        inited = true;
    }

    // fork: bucket build ∥ sgemm1 (g_cnt pre-zeroed: initial load or previous MEGA P5)
    cudaEventRecord(evA, 0);
    cudaStreamWaitEvent(sB, evA, 0);
    perm_kernel<<<(q8 + 255) / 256, 256, 0, sB>>>(ei, E);
    cudaEventRecord(evB, sB);

    sgemm1_att<<<NN / 32, 256>>>(x, W1, asrc1, adst1);

    cudaStreamWaitEvent(0, evB, 0);
    mega_kernel<<<G, 256>>>(b1, W2, asrc2, adst2, b2, out, G);
}

// round 15
// speedup vs baseline: 1.3209x; 1.3209x over previous
#include <cuda_runtime.h>
#include <cuda_fp16.h>
#include <math.h>

#define NN    8192
#define INC   512
#define SLOT  192
#define PMASK 0x7FFFFFFF

// ---------------- scratch (device globals) -----------------------------------
__device__ __half2 g_h1h[NN * 32];
__device__ float g_als1[NN * 8];
__device__ float g_ald1[NN * 8];
__device__ __half2 g_h2h[NN * 32];
__device__ float g_als2[NN];
__device__ float g_ald2[NN];
__device__ float g_x2[NN * 64];
__device__ __half2 g_s2h[NN * 32];
__device__ float g_tmp2[NN * 64];
__device__ float g_pool[2 * 4096];
__device__ float g_partA[128 * 4096];
__device__ float g_partX[128 * 4096];
__device__ int   g_cnt[NN];
__device__ __align__(16) int g_slot[NN * SLOT];

// ---------------- helpers ----------------------------------------------------
__device__ __forceinline__ float lrelu(float v) { return v > 0.f ? v : 0.2f * v; }

__device__ __forceinline__ void fma2(unsigned long long& d, unsigned long long a, unsigned long long b) {
    asm("fma.rn.f32x2 %0, %1, %2, %0;" : "+l"(d) : "l"(a), "l"(b));
}
__device__ __forceinline__ unsigned long long splat2(float a) {
    unsigned long long r;
    asm("mov.b64 %0, {%1, %1};" : "=l"(r) : "f"(a));
    return r;
}
__device__ __forceinline__ float4 ldh4(const __half2* p) {
    uint2 u = *(const uint2*)p;
    float2 a = __half22float2(*reinterpret_cast<__half2*>(&u.x));
    float2 b = __half22float2(*reinterpret_cast<__half2*>(&u.y));
    return make_float4(a.x, a.y, b.x, b.y);
}

// ---------------- bucket build (8 edges/thread) --------------------------------
__global__ void perm_kernel(const int* __restrict__ ei, int E) {
    int i = blockIdx.x * blockDim.x + threadIdx.x;
    int q8 = E >> 3;
    if (i < q8) {
        int4 sa = __ldg((const int4*)ei + 2 * i);
        int4 sb = __ldg((const int4*)ei + 2 * i + 1);
        int4 da = __ldg((const int4*)(ei + E) + 2 * i);
        int4 db = __ldg((const int4*)(ei + E) + 2 * i + 1);
        int p0 = atomicAdd(&g_cnt[da.x], 1);
        int p1 = atomicAdd(&g_cnt[da.y], 1);
        int p2 = atomicAdd(&g_cnt[da.z], 1);
        int p3 = atomicAdd(&g_cnt[da.w], 1);
        int p4 = atomicAdd(&g_cnt[db.x], 1);
        int p5 = atomicAdd(&g_cnt[db.y], 1);
        int p6 = atomicAdd(&g_cnt[db.z], 1);
        int p7 = atomicAdd(&g_cnt[db.w], 1);
        if (p0 < SLOT) g_slot[da.x * SLOT + p0] = sa.x;
        if (p1 < SLOT) g_slot[da.y * SLOT + p1] = sa.y;
        if (p2 < SLOT) g_slot[da.z * SLOT + p2] = sa.z;
        if (p3 < SLOT) g_slot[da.w * SLOT + p3] = sa.w;
        if (p4 < SLOT) g_slot[db.x * SLOT + p4] = sb.x;
        if (p5 < SLOT) g_slot[db.y * SLOT + p5] = sb.y;
        if (p6 < SLOT) g_slot[db.z * SLOT + p6] = sb.z;
        if (p7 < SLOT) g_slot[db.w * SLOT + p7] = sb.w;
    } else if (i < q8 + NN) {
        int n = i - q8;
        int p = atomicAdd(&g_cnt[n], 1);
        if (p < SLOT) g_slot[n * SLOT + p] = n | 0x80000000;
    }
}

// ---------------- sgemm1 (Kd=512, 32-row tiles) + att1, fp16 h1 out -------------
__global__ void sgemm1_att(const float* __restrict__ A, const float* __restrict__ B,
                           const float* __restrict__ asrc, const float* __restrict__ adst) {
    __shared__ float As[32][36];
    __shared__ float Bs[32][64];
    __shared__ float Cs[32][66];
    int tid = threadIdx.x;
    int row0 = blockIdx.x * 32;
    int ty = tid >> 4, tx = tid & 15;
    unsigned long long acc[2][2] = {};
    for (int k0 = 0; k0 < INC; k0 += 32) {
        #pragma unroll
        for (int i = tid; i < 32 * 32; i += 256) {
            int m = i >> 5, k = i & 31;
            As[k][m] = A[(row0 + m) * INC + k0 + k];
        }
        #pragma unroll
        for (int i = tid; i < 32 * 64; i += 256) {
            int k = i >> 6, n = i & 63;
            Bs[k][n] = B[(k0 + k) * 64 + n];
        }
        __syncthreads();
        #pragma unroll
        for (int k = 0; k < 32; k++) {
            float a0 = As[k][ty * 2], a1 = As[k][ty * 2 + 1];
            const unsigned long long* bp = (const unsigned long long*)&Bs[k][tx * 4];
            unsigned long long b01 = bp[0], b23 = bp[1];
            unsigned long long s0 = splat2(a0), s1 = splat2(a1);
            fma2(acc[0][0], s0, b01); fma2(acc[0][1], s0, b23);
            fma2(acc[1][0], s1, b01); fma2(acc[1][1], s1, b23);
        }
        __syncthreads();
    }
    #pragma unroll
    for (int i = 0; i < 2; i++) {
        float2 lo = *(float2*)&acc[i][0];
        float2 hi = *(float2*)&acc[i][1];
        __half2 ha = __floats2half2_rn(lo.x, lo.y);
        __half2 hb = __floats2half2_rn(hi.x, hi.y);
        uint2 u;
        u.x = *reinterpret_cast<unsigned*>(&ha);
        u.y = *reinterpret_cast<unsigned*>(&hb);
        *(uint2*)(g_h1h + (row0 + ty * 2 + i) * 32 + tx * 2) = u;
        unsigned long long* sp = (unsigned long long*)&Cs[ty * 2 + i][tx * 4];
        sp[0] = acc[i][0]; sp[1] = acc[i][1];
    }
    __syncthreads();
    {
        int n = tid >> 3, h = tid & 7;
        const float* hp = &Cs[n][h * 8];
        float s = 0.f, d = 0.f;
        #pragma unroll
        for (int c = 0; c < 8; c++) {
            s += hp[c] * __ldg(asrc + h * 8 + c);
            d += hp[c] * __ldg(adst + h * 8 + c);
        }
        g_als1[(row0 + n) * 8 + h] = s;
        g_ald1[(row0 + n) * 8 + h] = d;
    }
}

// ---------------- gather1 fused with sgemm2 + att2 (fp16 h1 in, fp16 h2 out) ----
__global__ void __launch_bounds__(256, 4)
gather1_fused(const float* __restrict__ b1, const float* __restrict__ W2,
              const float* __restrict__ asrc2, const float* __restrict__ adst2) {
    __shared__ __align__(16) float W2s[64 * 64];
    __shared__ float A2s[128];
    __shared__ __align__(16) float srow[8][64];
    int tid = threadIdx.x;
    #pragma unroll
    for (int i = tid; i < 64 * 64 / 4; i += 256)
        ((float4*)W2s)[i] = __ldg((const float4*)W2 + i);
    if (tid < 64)       A2s[tid] = __ldg(asrc2 + tid);
    else if (tid < 128) A2s[tid] = __ldg(adst2 + tid - 64);
    __syncthreads();

    int wid = tid >> 5;
    int node = blockIdx.x * 8 + wid;
    int lane = tid & 31;
    int epar = lane >> 4;
    int sub = lane & 15;
    int c0 = sub * 4;
    int h = sub >> 1;
    int cnt = min(__ldg(g_cnt + node), SLOT);
    int base = node * SLOT;
    float ald = __ldg(g_ald1 + node * 8 + h);
    float4 acc = make_float4(0.f, 0.f, 0.f, 0.f);
    float den = 0.f;
    int e = 0;
    int4 P = (8 <= cnt) ? *(const int4*)(g_slot + base + 4 * epar) : make_int4(0, 0, 0, 0);
    for (; e + 8 <= cnt; e += 8) {
        int4 Pn = (e + 16 <= cnt) ? *(const int4*)(g_slot + base + e + 8 + 4 * epar) : P;
        int p0 = P.x & PMASK, p1 = P.y & PMASK, p2 = P.z & PMASK, p3 = P.w & PMASK;
        float s0 = __ldg(g_als1 + p0 * 8 + h);
        float s1 = __ldg(g_als1 + p1 * 8 + h);
        float s2 = __ldg(g_als1 + p2 * 8 + h);
        float s3 = __ldg(g_als1 + p3 * 8 + h);
        float4 h0 = ldh4(g_h1h + p0 * 32 + sub * 2);
        float4 h1 = ldh4(g_h1h + p1 * 32 + sub * 2);
        float4 h2 = ldh4(g_h1h + p2 * 32 + sub * 2);
        float4 h3 = ldh4(g_h1h + p3 * 32 + sub * 2);
        float w0 = __expf(lrelu(s0 + ald));
        float w1 = __expf(lrelu(s1 + ald));
        float w2 = __expf(lrelu(s2 + ald));
        float w3 = __expf(lrelu(s3 + ald));
        den += (w0 + w1) + (w2 + w3);
        acc.x += w0 * h0.x + w1 * h1.x + w2 * h2.x + w3 * h3.x;
        acc.y += w0 * h0.y + w1 * h1.y + w2 * h2.y + w3 * h3.y;
        acc.z += w0 * h0.z + w1 * h1.z + w2 * h2.z + w3 * h3.z;
        acc.w += w0 * h0.w + w1 * h1.w + w2 * h2.w + w3 * h3.w;
        P = Pn;
    }
    for (; e < cnt; e++) {
        if (epar == 0) {
            int p = g_slot[base + e] & PMASK;
            float w = __expf(lrelu(__ldg(g_als1 + p * 8 + h) + ald));
            float4 hv = ldh4(g_h1h + p * 32 + sub * 2);
            den += w;
            acc.x += w * hv.x; acc.y += w * hv.y;
            acc.z += w * hv.z; acc.w += w * hv.w;
        }
    }
    acc.x += __shfl_xor_sync(0xffffffffu, acc.x, 16);
    acc.y += __shfl_xor_sync(0xffffffffu, acc.y, 16);
    acc.z += __shfl_xor_sync(0xffffffffu, acc.z, 16);
    acc.w += __shfl_xor_sync(0xffffffffu, acc.w, 16);
    den   += __shfl_xor_sync(0xffffffffu, den, 16);
    den += 1e-16f;
    float4 bb = *(const float4*)(b1 + c0);
    float4 v;
    v.x = acc.x / den + bb.x;
    v.y = acc.y / den + bb.y;
    v.z = acc.z / den + bb.z;
    v.w = acc.w / den + bb.w;
    v.x = v.x > 0.f ? v.x : (__expf(v.x) - 1.f);
    v.y = v.y > 0.f ? v.y : (__expf(v.y) - 1.f);
    v.z = v.z > 0.f ? v.z : (__expf(v.z) - 1.f);
    v.w = v.w > 0.f ? v.w : (__expf(v.w) - 1.f);
    if (epar == 0) *(float4*)&srow[wid][c0] = v;
    __syncwarp();
    // ---- h2 = row @ W2 (64x64) ----
    float4 ha = make_float4(0.f, 0.f, 0.f, 0.f);
    #pragma unroll
    for (int k4 = 0; k4 < 16; k4++) {
        float4 r = *(const float4*)&srow[wid][k4 * 4];
        float4 w0 = *(const float4*)&W2s[(k4 * 4 + 0) * 64 + c0];
        float4 w1 = *(const float4*)&W2s[(k4 * 4 + 1) * 64 + c0];
        float4 w2 = *(const float4*)&W2s[(k4 * 4 + 2) * 64 + c0];
        float4 w3 = *(const float4*)&W2s[(k4 * 4 + 3) * 64 + c0];
        ha.x += r.x * w0.x + r.y * w1.x + r.z * w2.x + r.w * w3.x;
        ha.y += r.x * w0.y + r.y * w1.y + r.z * w2.y + r.w * w3.y;
        ha.z += r.x * w0.z + r.y * w1.z + r.z * w2.z + r.w * w3.z;
        ha.w += r.x * w0.w + r.y * w1.w + r.z * w2.w + r.w * w3.w;
    }
    if (epar == 0) {
        __half2 hza = __floats2half2_rn(ha.x, ha.y);
        __half2 hzb = __floats2half2_rn(ha.z, ha.w);
        uint2 u;
        u.x = *reinterpret_cast<unsigned*>(&hza);
        u.y = *reinterpret_cast<unsigned*>(&hzb);
        *(uint2*)(g_h2h + node * 32 + sub * 2) = u;
    }
    // ---- att2 ----
    float s = ha.x * A2s[c0] + ha.y * A2s[c0 + 1] + ha.z * A2s[c0 + 2] + ha.w * A2s[c0 + 3];
    float d = ha.x * A2s[64 + c0] + ha.y * A2s[64 + c0 + 1]
            + ha.z * A2s[64 + c0 + 2] + ha.w * A2s[64 + c0 + 3];
    #pragma unroll
    for (int o = 1; o < 16; o <<= 1) {
        s += __shfl_xor_sync(0xffffffffu, s, o);
        d += __shfl_xor_sync(0xffffffffu, d, o);
    }
    if (lane == 0) { g_als2[node] = s; g_ald2[node] = d; }
}

// ---------------- layer-2 gather: pipelined two-phase, fp16 h2 ------------------
__global__ void __launch_bounds__(256, 5) gather2_kernel(const float* __restrict__ b2,
                                                         float* __restrict__ outS) {
    __shared__ uint2 stg[8][32];
    int tid = threadIdx.x;
    int wid = tid >> 5;
    int node = blockIdx.x * 8 + wid;
    int lane = tid & 31;
    int epar = lane >> 4;
    int sub = lane & 15;
    int c0 = sub * 4;
    int cnt = min(__ldg(g_cnt + node), SLOT);
    int base = node * SLOT;
    float ald = __ldg(g_ald2 + node);
    float4 acc = make_float4(0.f, 0.f, 0.f, 0.f);
    float den = 0.f;
    int p_cur = 0;
    float w_cur = 0.f;
    if (cnt > 0) {
        if (lane < cnt) p_cur = g_slot[base + lane] & PMASK;
        float als = __ldg(g_als2 + p_cur);
        w_cur = (lane < cnt) ? __expf(lrelu(als + ald)) : 0.f;
    }
    for (int e0 = 0; e0 < cnt; e0 += 32) {
        den += w_cur;
        stg[wid][lane] = make_uint2(__float_as_uint(w_cur), (unsigned)p_cur << 5);
        __syncwarp();
        int en = e0 + 32 + lane;
        bool vn = (en < cnt);
        int p_n = vn ? (g_slot[base + en] & PMASK) : 0;
        float als_n = __ldg(g_als2 + p_n);
        int lim = min(32, cnt - e0);
        int j = 0;
        for (; j + 8 <= lim; j += 8) {
            uint2 u0 = stg[wid][j + 0 + epar];
            uint2 u1 = stg[wid][j + 2 + epar];
            uint2 u2 = stg[wid][j + 4 + epar];
            uint2 u3 = stg[wid][j + 6 + epar];
            float4 h0 = ldh4(g_h2h + u0.y + sub * 2);
            float4 h1 = ldh4(g_h2h + u1.y + sub * 2);
            float4 h2v = ldh4(g_h2h + u2.y + sub * 2);
            float4 h3 = ldh4(g_h2h + u3.y + sub * 2);
            float w0 = __uint_as_float(u0.x);
            float w1 = __uint_as_float(u1.x);
            float w2 = __uint_as_float(u2.x);
            float w3 = __uint_as_float(u3.x);
            acc.x += w0 * h0.x + w1 * h1.x + w2 * h2v.x + w3 * h3.x;
            acc.y += w0 * h0.y + w1 * h1.y + w2 * h2v.y + w3 * h3.y;
            acc.z += w0 * h0.z + w1 * h1.z + w2 * h2v.z + w3 * h3.z;
            acc.w += w0 * h0.w + w1 * h1.w + w2 * h2v.w + w3 * h3.w;
        }
        for (; j < lim; j += 2) {
            uint2 u = stg[wid][j + epar];
            float wj = __uint_as_float(u.x);
            float4 hv = ldh4(g_h2h + u.y + sub * 2);
            acc.x += wj * hv.x; acc.y += wj * hv.y;
            acc.z += wj * hv.z; acc.w += wj * hv.w;
        }
        __syncwarp();
        w_cur = vn ? __expf(lrelu(als_n + ald)) : 0.f;
        p_cur = p_n;
    }
    acc.x += __shfl_xor_sync(0xffffffffu, acc.x, 16);
    acc.y += __shfl_xor_sync(0xffffffffu, acc.y, 16);
    acc.z += __shfl_xor_sync(0xffffffffu, acc.z, 16);
    acc.w += __shfl_xor_sync(0xffffffffu, acc.w, 16);
    #pragma unroll
    for (int o = 16; o > 0; o >>= 1) den += __shfl_xor_sync(0xffffffffu, den, o);
    den += 1e-16f;
    float4 bb = *(const float4*)(b2 + c0);
    float4 v;
    v.x = acc.x / den + bb.x;
    v.y = acc.y / den + bb.y;
    v.z = acc.z / den + bb.z;
    v.w = acc.w / den + bb.w;
    if (epar == 0) *(float4*)(g_x2 + node * 64 + c0) = v;
    float mx = fmaxf(fmaxf(v.x, v.y), fmaxf(v.z, v.w));
    #pragma unroll
    for (int o = 1; o < 16; o <<= 1) mx = fmaxf(mx, __shfl_xor_sync(0xffffffffu, mx, o));
    float e0v = __expf(v.x - mx), e1v = __expf(v.y - mx);
    float e2v = __expf(v.z - mx), e3v = __expf(v.w - mx);
    float sm = (e0v + e1v) + (e2v + e3v);
    #pragma unroll
    for (int o = 1; o < 16; o <<= 1) sm += __shfl_xor_sync(0xffffffffu, sm, o);
    float4 s;
    s.x = e0v / sm; s.y = e1v / sm; s.z = e2v / sm; s.w = e3v / sm;
    if (epar == 0) *(float4*)(outS + node * 64 + c0) = s;
    float m2 = fmaxf(fmaxf(s.x, s.y), fmaxf(s.z, s.w));
    #pragma unroll
    for (int o = 1; o < 16; o <<= 1) m2 = fmaxf(m2, __shfl_xor_sync(0xffffffffu, m2, o));
    float f0 = __expf(s.x - m2), f1 = __expf(s.y - m2);
    float f2 = __expf(s.z - m2), f3 = __expf(s.w - m2);
    float sm2 = (f0 + f1) + (f2 + f3);
    #pragma unroll
    for (int o = 1; o < 16; o <<= 1) sm2 += __shfl_xor_sync(0xffffffffu, sm2, o);
    float4 z;
    z.x = f0 / sm2; z.y = f1 / sm2; z.z = f2 / sm2; z.w = f3 / sm2;
    if (epar == 0) {
        __half2 hza = __floats2half2_rn(z.x, z.y);
        __half2 hzb = __floats2half2_rn(z.z, z.w);
        uint2 u;
        u.x = *reinterpret_cast<unsigned*>(&hza);
        u.y = *reinterpret_cast<unsigned*>(&hzb);
        *(uint2*)(g_s2h + node * 32 + sub * 2) = u;
    }
}

// ---------------- adjacency gather (fp16 s2, slot prefetch) ---------------------
__global__ void __launch_bounds__(256, 5) adj_gather_kernel() {
    int node = (blockIdx.x * blockDim.x + threadIdx.x) >> 5;
    if (node >= NN) return;
    int lane = threadIdx.x & 31;
    int epar = lane >> 4;
    int sub = lane & 15;
    int cnt = min(__ldg(g_cnt + node), SLOT);
    int base = node * SLOT;
    float4 acc = make_float4(0.f, 0.f, 0.f, 0.f);
    int e = 0;
    int4 P = (8 <= cnt) ? *(const int4*)(g_slot + base + 4 * epar)
                        : make_int4(-1, -1, -1, -1);
    for (; e + 8 <= cnt; e += 8) {
        int4 Pn = (e + 16 <= cnt) ? *(const int4*)(g_slot + base + e + 8 + 4 * epar) : P;
        float4 f0 = ldh4(g_s2h + (P.x & PMASK) * 32 + sub * 2);
        float4 f1 = ldh4(g_s2h + (P.y & PMASK) * 32 + sub * 2);
        float4 f2 = ldh4(g_s2h + (P.z & PMASK) * 32 + sub * 2);
        float4 f3 = ldh4(g_s2h + (P.w & PMASK) * 32 + sub * 2);
        if (P.x >= 0) { acc.x += f0.x; acc.y += f0.y; acc.z += f0.z; acc.w += f0.w; }
        if (P.y >= 0) { acc.x += f1.x; acc.y += f1.y; acc.z += f1.z; acc.w += f1.w; }
        if (P.z >= 0) { acc.x += f2.x; acc.y += f2.y; acc.z += f2.z; acc.w += f2.w; }
        if (P.w >= 0) { acc.x += f3.x; acc.y += f3.y; acc.z += f3.z; acc.w += f3.w; }
        P = Pn;
    }
    for (; e < cnt; e++) {
        if (epar == 0) {
            int p = g_slot[base + e];
            if (p >= 0) {
                float4 fv = ldh4(g_s2h + (p & PMASK) * 32 + sub * 2);
                acc.x += fv.x; acc.y += fv.y; acc.z += fv.z; acc.w += fv.w;
            }
        }
    }
    acc.x += __shfl_xor_sync(0xffffffffu, acc.x, 16);
    acc.y += __shfl_xor_sync(0xffffffffu, acc.y, 16);
    acc.z += __shfl_xor_sync(0xffffffffu, acc.z, 16);
    acc.w += __shfl_xor_sync(0xffffffffu, acc.w, 16);
    if (epar == 0)
        *(float4*)(g_tmp2 + node * 64 + sub * 4) = acc;
}

// ---------------- pool partials: X part (s2^T x2), s2 from fp16 -----------------
__global__ void poolX_part() {
    int i = threadIdx.x >> 2;
    int jb = (threadIdx.x & 3) * 16;
    int chunk = blockIdx.x;
    int base = chunk * 64;
    const __half* s2half = (const __half*)g_s2h;
    float accX[16] = {};
    for (int n = 0; n < 64; n++) {
        int node = base + n;
        float si = __half2float(s2half[node * 64 + i]);
        const float4* x4 = (const float4*)(g_x2 + node * 64 + jb);
        #pragma unroll
        for (int q = 0; q < 4; q++) {
            float4 xv = __ldg(x4 + q);
            accX[q * 4 + 0] += si * xv.x; accX[q * 4 + 1] += si * xv.y;
            accX[q * 4 + 2] += si * xv.z; accX[q * 4 + 3] += si * xv.w;
        }
    }
    float* pa = g_partX + chunk * 4096;
    #pragma unroll
    for (int u = 0; u < 16; u++) pa[i * 64 + jb + u] = accX[u];
}

// ---------------- pool partials: A part (s2^T tmp2), s2 from fp16 ---------------
__global__ void poolA_part() {
    int i = threadIdx.x >> 2;
    int jb = (threadIdx.x & 3) * 16;
    int chunk = blockIdx.x;
    int base = chunk * 64;
    const __half* s2half = (const __half*)g_s2h;
    float accA[16] = {};
    for (int n = 0; n < 64; n++) {
        int node = base + n;
        float si = __half2float(s2half[node * 64 + i]);
        const float4* t4 = (const float4*)(g_tmp2 + node * 64 + jb);
        #pragma unroll
        for (int q = 0; q < 4; q++) {
            float4 tv = __ldg(t4 + q);
            accA[q * 4 + 0] += si * tv.x; accA[q * 4 + 1] += si * tv.y;
            accA[q * 4 + 2] += si * tv.z; accA[q * 4 + 3] += si * tv.w;
        }
    }
    float* pa = g_partA + chunk * 4096;
    #pragma unroll
    for (int u = 0; u < 16; u++) pa[i * 64 + jb + u] = accA[u];
}

// ---------------- reduce partials -----------------------------------------------
__global__ void reduceP() {
    int idx = blockIdx.x * blockDim.x + threadIdx.x;
    if (idx >= 8192) return;
    float s = 0.f;
    if (idx < 4096) {
        #pragma unroll 8
        for (int b = 0; b < 128; b++) s += g_partA[b * 4096 + idx];
    } else {
        int j = idx - 4096;
        #pragma unroll 8
        for (int b = 0; b < 128; b++) s += g_partX[b * 4096 + j];
    }
    g_pool[idx] = s;
}

// ---------------- finalize ------------------------------------------------------
__global__ void finalize(float* __restrict__ out) {
    __shared__ float sd[64];
    int i = threadIdx.x;
    float rs = 0.f;
    for (int j = 0; j < 64; j++) {
        float v = (j == i) ? 0.f : g_pool[i * 64 + j];
        rs += v;
    }
    sd[i] = sqrtf(rs) + 1e-15f;
    __syncthreads();
    for (int j = 0; j < 64; j++) {
        float v = (j == i) ? 0.f : g_pool[i * 64 + j];
        out[4096 + i * 64 + j] = v / sd[j] / sd[i];
        out[i * 64 + j] = g_pool[4096 + i * 64 + j];
    }
}

// ---------------- launch --------------------------------------------------------
extern "C" void kernel_launch(void* const* d_in, const int* in_sizes, int n_in,
                              void* d_out, int out_size) {
    const float* x     = (const float*)d_in[0];
    const int*   ei    = (const int*)d_in[1];
    const float* W1    = (const float*)d_in[2];
    const float* asrc1 = (const float*)d_in[3];
    const float* adst1 = (const float*)d_in[4];
    const float* b1    = (const float*)d_in[5];
    const float* W2    = (const float*)d_in[6];
    const float* asrc2 = (const float*)d_in[7];
    const float* adst2 = (const float*)d_in[8];
    const float* b2    = (const float*)d_in[9];
    float* out = (float*)d_out;

    const int E = in_sizes[1] / 2;       // 524288
    const int q8 = (E >> 3) + NN;

    static bool inited = false;
    static cudaStream_t sB;
    static cudaEvent_t evA, evB, evC, evD;
    if (!inited) {
        cudaStreamCreateWithFlags(&sB, cudaStreamNonBlocking);
        cudaEventCreateWithFlags(&evA, cudaEventDisableTiming);
        cudaEventCreateWithFlags(&evB, cudaEventDisableTiming);
        cudaEventCreateWithFlags(&evC, cudaEventDisableTiming);
        cudaEventCreateWithFlags(&evD, cudaEventDisableTiming);
        inited = true;
    }

    int *cntp;
    cudaGetSymbolAddress((void**)&cntp, g_cnt);

    cudaMemsetAsync(cntp, 0, NN * sizeof(int), 0);

    // fork 1: bucket build ∥ sgemm1
    cudaEventRecord(evA, 0);
    cudaStreamWaitEvent(sB, evA, 0);
    perm_kernel<<<(q8 + 255) / 256, 256, 0, sB>>>(ei, E);
    cudaEventRecord(evB, sB);

    sgemm1_att<<<NN / 32, 256>>>(x, W1, asrc1, adst1);

    cudaStreamWaitEvent(0, evB, 0);
    gather1_fused<<<NN / 8, 256>>>(b1, W2, asrc2, adst2);
    gather2_kernel<<<NN / 8, 256>>>(b2, out + 2 * 4096);

    // fork 2: poolX ∥ adj_gather
    cudaEventRecord(evC, 0);
    cudaStreamWaitEvent(sB, evC, 0);
    poolX_part<<<128, 256, 0, sB>>>();
    cudaEventRecord(evD, sB);

    adj_gather_kernel<<<NN * 32 / 256, 256>>>();
    poolA_part<<<128, 256>>>();

    cudaStreamWaitEvent(0, evD, 0);
    reduceP<<<64, 128>>>();
    finalize<<<1, 64>>>(out);
}